// round 4
// baseline (speedup 1.0000x reference)
#include <cuda_runtime.h>
#include <cstdint>

#define UNITS 65
#define G4    260          // 4*UNITS
#define BATCH 50
#define SEQ   8192
#define NROWS (BATCH * SEQ)   // 409600

// ---------------- scratch (device globals; no runtime allocation) ----------------
__device__ float g_zpre[(size_t)NROWS * G4];   // x@W + b, precomputed per (b,t)
__device__ float g_h3[(size_t)NROWS * UNITS];  // layer-3 hidden states (ys)

// ---------------- f32x2 helpers (Blackwell packed fp32 FMA) ----------------
__device__ __forceinline__ unsigned long long pack2(float lo, float hi) {
    unsigned long long v;
    asm("mov.b64 %0, {%1, %2};" : "=l"(v) : "f"(lo), "f"(hi));
    return v;
}
__device__ __forceinline__ unsigned long long ffma2(unsigned long long a,
                                                    unsigned long long b,
                                                    unsigned long long c) {
    unsigned long long d;
    asm("fma.rn.f32x2 %0, %1, %2, %3;" : "=l"(d) : "l"(a), "l"(b), "l"(c));
    return d;
}
__device__ __forceinline__ unsigned long long fadd2(unsigned long long a,
                                                    unsigned long long b) {
    unsigned long long d;
    asm("add.rn.f32x2 %0, %1, %2;" : "=l"(d) : "l"(a), "l"(b));
    return d;
}
__device__ __forceinline__ float hsum4(unsigned long long a0, unsigned long long a1) {
    unsigned long long s = fadd2(a0, a1);
    float x0, x1;
    asm("mov.b64 {%0, %1}, %2;" : "=f"(x0), "=f"(x1) : "l"(s));
    return x0 + x1;
}

// dot over K=65 (padded to 66 with zero): sh must be 16B-aligned float[68] with
// sh[65] == 0; col[33] holds weight pairs (col[32].hi == 0).
__device__ __forceinline__ void dot33(const float* __restrict__ sh,
                                      const unsigned long long* col,
                                      unsigned long long& a0,
                                      unsigned long long& a1) {
    const ulonglong2* hp = reinterpret_cast<const ulonglong2*>(sh);
#pragma unroll
    for (int m = 0; m < 16; m++) {
        ulonglong2 p = hp[m];
        a0 = ffma2(p.x, col[2 * m + 0], a0);
        a1 = ffma2(p.y, col[2 * m + 1], a1);
    }
    unsigned long long last = *reinterpret_cast<const unsigned long long*>(sh + 64);
    a0 = ffma2(last, col[32], a0);
}

// ---------------- fast activations (ex2/rcp approx: ~1e-6 rel err) ----------------
__device__ __forceinline__ float fast_ex2(float x) {
    float y; asm("ex2.approx.f32 %0, %1;" : "=f"(y) : "f"(x)); return y;
}
__device__ __forceinline__ float fast_rcp(float x) {
    float y; asm("rcp.approx.f32 %0, %1;" : "=f"(y) : "f"(x)); return y;
}
#define LOG2E 1.4426950408889634f
__device__ __forceinline__ float sigm_f(float x) {
    return fast_rcp(1.0f + fast_ex2(-x * LOG2E));
}
__device__ __forceinline__ float tanh_f(float x) {
    return fmaf(-2.0f, fast_rcp(1.0f + fast_ex2(2.0f * LOG2E * x)), 1.0f);
}

// ---------------- kernel 1: zpre = x @ W + b  (all rows, parallel) ----------------
__global__ void __launch_bounds__(G4) pre_kernel(const float* __restrict__ x,
                                                 const float* __restrict__ W,
                                                 const float* __restrict__ b) {
    const int tid = threadIdx.x;           // 0..259  -> gate column
    const int rsub = tid / UNITS;          // 0..3    (x-row loader role)
    const int jl = tid - rsub * UNITS;     // 0..64

    unsigned long long wcol[33];
#pragma unroll
    for (int m = 0; m < 32; m++)
        wcol[m] = pack2(W[(2 * m) * G4 + tid], W[(2 * m + 1) * G4 + tid]);
    wcol[32] = pack2(W[64 * G4 + tid], 0.0f);
    const float bj = b[tid];

    __shared__ __align__(16) float sh_x[4][68];
    if (tid < 12) sh_x[tid / 3][65 + tid % 3] = 0.0f;   // zero pads once
    __syncthreads();

    for (size_t row0 = (size_t)blockIdx.x * 4; row0 < NROWS;
         row0 += (size_t)gridDim.x * 4) {
        __syncthreads();   // previous iteration's reads complete
        sh_x[rsub][jl] = x[(row0 + rsub) * UNITS + jl];
        __syncthreads();
#pragma unroll
        for (int r = 0; r < 4; r++) {
            unsigned long long a0 = 0ull, a1 = 0ull;
            dot33(sh_x[r], wcol, a0, a1);
            g_zpre[(row0 + r) * G4 + tid] = bj + hsum4(a0, a1);
        }
    }
}

// ---------------- kernel 2: persistent recurrence, one block per batch row ----------
// 352 threads: j<260 = GEMV ("dot") threads, weights in registers.
//              j in [288,321) = 33 dedicated activation threads (2 units each).
// 5 balanced phases per step, one 33-FFMA2 dot each; activations fully
// overlapped with an independent dot so no warp ever runs act+dot serially.
__global__ void __launch_bounds__(352, 1) rec_kernel(const float* __restrict__ W,
                                                     const float* __restrict__ U,
                                                     const float* __restrict__ b) {
    const int j = threadIdx.x;
    const int row = blockIdx.x;

    __shared__ __align__(16) float sh_h1[68], sh_h2[68], sh_h3[68];
    __shared__ float sh_z1[G4], sh_z2[G4], sh_z3[G4];

    const bool is_dot = (j < G4);
    const int ak = j - 288;                 // activation thread index
    const bool is_act = (ak >= 0) && (ak < 33);
    const int u0 = 2 * ak;                  // unit pair handled by act thread
    const int u1v = 2 * ak + 1;
    const bool has_u1 = (u1v < UNITS);

    unsigned long long wcol[33], ucol[33];
    float bj = 0.0f;
    if (is_dot) {
#pragma unroll
        for (int m = 0; m < 32; m++) {
            wcol[m] = pack2(W[(2 * m) * G4 + j], W[(2 * m + 1) * G4 + j]);
            ucol[m] = pack2(U[(2 * m) * G4 + j], U[(2 * m + 1) * G4 + j]);
        }
        wcol[32] = pack2(W[64 * G4 + j], 0.0f);
        ucol[32] = pack2(U[64 * G4 + j], 0.0f);
        bj = b[j];
    }
    if (j < 68) { sh_h1[j] = 0.0f; sh_h2[j] = 0.0f; sh_h3[j] = 0.0f; }

    const float* __restrict__ zpre = g_zpre + (size_t)row * SEQ * G4;
    float* __restrict__ h3out = g_h3 + (size_t)row * SEQ * UNITS;

    // accumulators held across phases
    unsigned long long au1_0 = 0ull, au1_1 = 0ull;   // h1(t)@U  -> z1(t+1)
    unsigned long long au2_0 = 0ull, au2_1 = 0ull;   // h2(t-1)@U -> z2(t)
    unsigned long long au3_0 = 0ull, au3_1 = 0ull;   // h3(t-1)@U -> z3(t)
    float zp = 0.0f;                                  // zpre(t+1) prefetch

    // cell states (per activation thread, 2 units x 3 layers)
    float c1a = 0.f, c1b = 0.f, c2a = 0.f, c2b = 0.f, c3a = 0.f, c3b = 0.f;

    if (is_dot) sh_z1[j] = zpre[j];   // z1(0) = zpre(0)  (h1(-1)=0)
    __syncthreads();

    for (int t = 0; t < SEQ; t++) {
        // ---- P1: act L1  ||  u3 = h3(t-1)@U, prefetch zpre(t+1) ----
        if (is_dot) {
            au3_0 = 0ull; au3_1 = 0ull;
            dot33(sh_h3, ucol, au3_0, au3_1);
            int tn = (t + 1 < SEQ) ? t + 1 : t;
            zp = zpre[(size_t)tn * G4 + j];
        } else if (is_act) {
            {
                float zi = sh_z1[u0], zf = sh_z1[u0 + UNITS];
                float zg = sh_z1[u0 + 2 * UNITS], zo = sh_z1[u0 + 3 * UNITS];
                c1a = sigm_f(zf) * c1a + sigm_f(zi) * tanh_f(zg);
                sh_h1[u0] = sigm_f(zo) * tanh_f(c1a);
            }
            if (has_u1) {
                float zi = sh_z1[u1v], zf = sh_z1[u1v + UNITS];
                float zg = sh_z1[u1v + 2 * UNITS], zo = sh_z1[u1v + 3 * UNITS];
                c1b = sigm_f(zf) * c1b + sigm_f(zi) * tanh_f(zg);
                sh_h1[u1v] = sigm_f(zo) * tanh_f(c1b);
            }
        }
        __syncthreads();

        // ---- P2: z2 = h1(t)@W + u2 + b ----
        if (is_dot) {
            unsigned long long a0 = au2_0, a1 = au2_1;
            dot33(sh_h1, wcol, a0, a1);
            sh_z2[j] = bj + hsum4(a0, a1);
        }
        __syncthreads();

        // ---- P3: act L2  ||  u1(next) = h1(t)@U ----
        if (is_dot) {
            au1_0 = 0ull; au1_1 = 0ull;
            dot33(sh_h1, ucol, au1_0, au1_1);
        } else if (is_act) {
            {
                float zi = sh_z2[u0], zf = sh_z2[u0 + UNITS];
                float zg = sh_z2[u0 + 2 * UNITS], zo = sh_z2[u0 + 3 * UNITS];
                c2a = sigm_f(zf) * c2a + sigm_f(zi) * tanh_f(zg);
                sh_h2[u0] = sigm_f(zo) * tanh_f(c2a);
            }
            if (has_u1) {
                float zi = sh_z2[u1v], zf = sh_z2[u1v + UNITS];
                float zg = sh_z2[u1v + 2 * UNITS], zo = sh_z2[u1v + 3 * UNITS];
                c2b = sigm_f(zf) * c2b + sigm_f(zi) * tanh_f(zg);
                sh_h2[u1v] = sigm_f(zo) * tanh_f(c2b);
            }
        }
        __syncthreads();

        // ---- P4: z3 = h2(t)@W + u3 + b ----
        if (is_dot) {
            unsigned long long a0 = au3_0, a1 = au3_1;
            dot33(sh_h2, wcol, a0, a1);
            sh_z3[j] = bj + hsum4(a0, a1);
        }
        __syncthreads();

        // ---- P5: act L3 (+emit h3)  ||  u2(next) = h2(t)@U, z1(next) = zpre + u1 ----
        if (is_dot) {
            au2_0 = 0ull; au2_1 = 0ull;
            dot33(sh_h2, ucol, au2_0, au2_1);
            sh_z1[j] = zp + hsum4(au1_0, au1_1);
        } else if (is_act) {
            {
                float zi = sh_z3[u0], zf = sh_z3[u0 + UNITS];
                float zg = sh_z3[u0 + 2 * UNITS], zo = sh_z3[u0 + 3 * UNITS];
                c3a = sigm_f(zf) * c3a + sigm_f(zi) * tanh_f(zg);
                float hn = sigm_f(zo) * tanh_f(c3a);
                sh_h3[u0] = hn;
                h3out[(size_t)t * UNITS + u0] = hn;
            }
            if (has_u1) {
                float zi = sh_z3[u1v], zf = sh_z3[u1v + UNITS];
                float zg = sh_z3[u1v + 2 * UNITS], zo = sh_z3[u1v + 3 * UNITS];
                c3b = sigm_f(zf) * c3b + sigm_f(zi) * tanh_f(zg);
                float hn = sigm_f(zo) * tanh_f(c3b);
                sh_h3[u1v] = hn;
                h3out[(size_t)t * UNITS + u1v] = hn;
            }
        }
        __syncthreads();
    }
}

// ---------------- kernel 3: out = ys @ Wd + bd  (parallel) ----------------
__global__ void __launch_bounds__(G4) dense_kernel(const float* __restrict__ Wd,
                                                   const float* __restrict__ bd,
                                                   float* __restrict__ out) {
    const int tid = threadIdx.x;           // 0..259
    const int rsub = tid / UNITS;          // 0..3
    const int jl = tid - rsub * UNITS;     // 0..64 -> output column

    unsigned long long wdcol[33];
#pragma unroll
    for (int m = 0; m < 32; m++)
        wdcol[m] = pack2(Wd[(2 * m) * UNITS + jl], Wd[(2 * m + 1) * UNITS + jl]);
    wdcol[32] = pack2(Wd[64 * UNITS + jl], 0.0f);
    const float bj = bd[jl];

    __shared__ __align__(16) float sh_y[4][68];
    if (tid < 12) sh_y[tid / 3][65 + tid % 3] = 0.0f;
    __syncthreads();

    for (size_t row0 = (size_t)blockIdx.x * 4; row0 < NROWS;
         row0 += (size_t)gridDim.x * 4) {
        __syncthreads();
        sh_y[rsub][jl] = g_h3[(row0 + rsub) * UNITS + jl];
        __syncthreads();
        unsigned long long a0 = 0ull, a1 = 0ull;
        dot33(sh_y[rsub], wdcol, a0, a1);
        out[(row0 + rsub) * UNITS + jl] = bj + hsum4(a0, a1);
    }
}

// ---------------- launch ----------------
extern "C" void kernel_launch(void* const* d_in, const int* in_sizes, int n_in,
                              void* d_out, int out_size) {
    const float* x  = (const float*)d_in[0];
    const float* W  = (const float*)d_in[1];
    const float* U  = (const float*)d_in[2];
    const float* b  = (const float*)d_in[3];
    const float* Wd = (const float*)d_in[4];
    const float* bd = (const float*)d_in[5];
    float* out = (float*)d_out;

    pre_kernel<<<1184, G4>>>(x, W, b);
    rec_kernel<<<BATCH, 352>>>(W, U, b);
    dense_kernel<<<1184, G4>>>(Wd, bd, out);
}

// round 5
// speedup vs baseline: 1.3868x; 1.3868x over previous
#include <cuda_runtime.h>
#include <cstdint>

#define UNITS 65
#define G4    260          // 4*UNITS
#define BATCH 50
#define SEQ   8192
#define NROWS (BATCH * SEQ)   // 409600

// ---------------- scratch (device globals; no runtime allocation) ----------------
__device__ float g_zpre[(size_t)NROWS * G4];   // x@W + b, precomputed per (b,t)
__device__ float g_h3[(size_t)NROWS * UNITS];  // layer-3 hidden states (ys)

// ---------------- f32x2 helpers (Blackwell packed fp32 FMA) ----------------
__device__ __forceinline__ unsigned long long pack2(float lo, float hi) {
    unsigned long long v;
    asm("mov.b64 %0, {%1, %2};" : "=l"(v) : "f"(lo), "f"(hi));
    return v;
}
__device__ __forceinline__ unsigned long long ffma2(unsigned long long a,
                                                    unsigned long long b,
                                                    unsigned long long c) {
    unsigned long long d;
    asm("fma.rn.f32x2 %0, %1, %2, %3;" : "=l"(d) : "l"(a), "l"(b), "l"(c));
    return d;
}
__device__ __forceinline__ unsigned long long fadd2(unsigned long long a,
                                                    unsigned long long b) {
    unsigned long long d;
    asm("add.rn.f32x2 %0, %1, %2;" : "=l"(d) : "l"(a), "l"(b));
    return d;
}
__device__ __forceinline__ float hsum4(unsigned long long a0, unsigned long long a1) {
    unsigned long long s = fadd2(a0, a1);
    float x0, x1;
    asm("mov.b64 {%0, %1}, %2;" : "=f"(x0), "=f"(x1) : "l"(s));
    return x0 + x1;
}

// dot over K=65 (padded to 66 with zero): sh must be 16B-aligned float[68] with
// sh[65] == 0; col[33] holds weight pairs (col[32].hi == 0).
__device__ __forceinline__ void dot33(const float* __restrict__ sh,
                                      const unsigned long long* col,
                                      unsigned long long& a0,
                                      unsigned long long& a1) {
    const ulonglong2* hp = reinterpret_cast<const ulonglong2*>(sh);
#pragma unroll
    for (int m = 0; m < 16; m++) {
        ulonglong2 p = hp[m];
        a0 = ffma2(p.x, col[2 * m + 0], a0);
        a1 = ffma2(p.y, col[2 * m + 1], a1);
    }
    unsigned long long last = *reinterpret_cast<const unsigned long long*>(sh + 64);
    a0 = ffma2(last, col[32], a0);
}

// ---------------- fast activations (ex2/rcp approx: ~1e-6 rel err) ----------------
__device__ __forceinline__ float fast_ex2(float x) {
    float y; asm("ex2.approx.f32 %0, %1;" : "=f"(y) : "f"(x)); return y;
}
__device__ __forceinline__ float fast_rcp(float x) {
    float y; asm("rcp.approx.f32 %0, %1;" : "=f"(y) : "f"(x)); return y;
}
#define LOG2E 1.4426950408889634f
__device__ __forceinline__ float sigm_f(float x) {
    return fast_rcp(1.0f + fast_ex2(-x * LOG2E));
}
__device__ __forceinline__ float tanh_f(float x) {
    return fmaf(-2.0f, fast_rcp(1.0f + fast_ex2(2.0f * LOG2E * x)), 1.0f);
}

// ---------------- kernel 1: zpre = x @ W + b  (all rows, parallel) ----------------
__global__ void __launch_bounds__(G4) pre_kernel(const float* __restrict__ x,
                                                 const float* __restrict__ W,
                                                 const float* __restrict__ b) {
    const int tid = threadIdx.x;           // 0..259  -> gate column
    const int rsub = tid / UNITS;          // 0..3    (x-row loader role)
    const int jl = tid - rsub * UNITS;     // 0..64

    unsigned long long wcol[33];
#pragma unroll
    for (int m = 0; m < 32; m++)
        wcol[m] = pack2(W[(2 * m) * G4 + tid], W[(2 * m + 1) * G4 + tid]);
    wcol[32] = pack2(W[64 * G4 + tid], 0.0f);
    const float bj = b[tid];

    __shared__ __align__(16) float sh_x[4][68];
    if (tid < 12) sh_x[tid / 3][65 + tid % 3] = 0.0f;   // zero pads once
    __syncthreads();

    for (size_t row0 = (size_t)blockIdx.x * 4; row0 < NROWS;
         row0 += (size_t)gridDim.x * 4) {
        __syncthreads();   // previous iteration's reads complete
        sh_x[rsub][jl] = x[(row0 + rsub) * UNITS + jl];
        __syncthreads();
#pragma unroll
        for (int r = 0; r < 4; r++) {
            unsigned long long a0 = 0ull, a1 = 0ull;
            dot33(sh_x[r], wcol, a0, a1);
            g_zpre[(row0 + r) * G4 + tid] = bj + hsum4(a0, a1);
        }
    }
}

// ---------------- kernel 2: persistent recurrence, one block per batch row ----------
// 352 threads, warp-aligned roles:
//   warps 0-8 : dot threads (j < 260 active), weights in registers.
//   warps 9-10: activation threads (j in [288,352)), ONE unit each (j==288 also
//               handles unit 64). No warp mixes dot and act work.
// 5 phases/step, 5 barriers. Exactly ONE accumulator pair (a0,a1) live at any
// time (same register profile as the 13.2ms R2 kernel -> no spills), unlike the
// regressed R4 version which held 3 pairs and spilled at the 184-reg cap.
__global__ void __launch_bounds__(352, 1) rec_kernel(const float* __restrict__ W,
                                                     const float* __restrict__ U,
                                                     const float* __restrict__ b) {
    const int j = threadIdx.x;
    const int row = blockIdx.x;

    __shared__ __align__(16) float sh_h1[68], sh_h2[68], sh_h3[68];
    __shared__ float sh_z1[G4], sh_z2[G4], sh_z3[G4];

    const bool is_dot = (j < G4);
    const int ak = j - 288;                  // activation unit (warps 9-10)
    const bool is_act = (ak >= 0);           // j in [288,352)
    const bool has_u2 = (ak == 0);           // thread 288 also owns unit 64

    unsigned long long wcol[33], ucol[33];
    float bj = 0.0f;
    if (is_dot) {
#pragma unroll
        for (int m = 0; m < 32; m++) {
            wcol[m] = pack2(W[(2 * m) * G4 + j], W[(2 * m + 1) * G4 + j]);
            ucol[m] = pack2(U[(2 * m) * G4 + j], U[(2 * m + 1) * G4 + j]);
        }
        wcol[32] = pack2(W[64 * G4 + j], 0.0f);
        ucol[32] = pack2(U[64 * G4 + j], 0.0f);
        bj = b[j];
    }
    if (j < 68) { sh_h1[j] = 0.0f; sh_h2[j] = 0.0f; sh_h3[j] = 0.0f; }

    const float* __restrict__ zpre = g_zpre + (size_t)row * SEQ * G4;
    float* __restrict__ h3out = g_h3 + (size_t)row * SEQ * UNITS;

    unsigned long long a0 = 0ull, a1 = 0ull;   // the ONLY live accumulator pair
    float zp = 0.0f;                            // zpre(t+1) prefetch

    // cell states: one unit per act thread (+ unit 64 on thread 288)
    float c1 = 0.f, c2 = 0.f, c3 = 0.f;
    float c1x = 0.f, c2x = 0.f, c3x = 0.f;

    if (is_dot) sh_z1[j] = zpre[j];   // z1(0) = zpre(0)  (h1(-1)=0)
    __syncthreads();

    for (int t = 0; t < SEQ; t++) {
        // ---- B: act L1 (->sh_h1)  ||  u2 = h2(t-1)@U, prefetch zpre(t+1) ----
        if (is_dot) {
            a0 = 0ull; a1 = 0ull;
            dot33(sh_h2, ucol, a0, a1);
            int tn = (t + 1 < SEQ) ? t + 1 : t;
            zp = zpre[(size_t)tn * G4 + j];
        } else if (is_act) {
            {
                float zi = sh_z1[ak], zf = sh_z1[ak + UNITS];
                float zg = sh_z1[ak + 2 * UNITS], zo = sh_z1[ak + 3 * UNITS];
                c1 = sigm_f(zf) * c1 + sigm_f(zi) * tanh_f(zg);
                sh_h1[ak] = sigm_f(zo) * tanh_f(c1);
            }
            if (has_u2) {
                float zi = sh_z1[64], zf = sh_z1[64 + UNITS];
                float zg = sh_z1[64 + 2 * UNITS], zo = sh_z1[64 + 3 * UNITS];
                c1x = sigm_f(zf) * c1x + sigm_f(zi) * tanh_f(zg);
                sh_h1[64] = sigm_f(zo) * tanh_f(c1x);
            }
        }
        __syncthreads();

        // ---- C: z2 = h1(t)@W + u2 + b ----
        if (is_dot) {
            dot33(sh_h1, wcol, a0, a1);
            sh_z2[j] = bj + hsum4(a0, a1);
        }
        __syncthreads();

        // ---- D: act L2 (->sh_h2)  ||  u3 = h3(t-1)@U ----
        if (is_dot) {
            a0 = 0ull; a1 = 0ull;
            dot33(sh_h3, ucol, a0, a1);
        } else if (is_act) {
            {
                float zi = sh_z2[ak], zf = sh_z2[ak + UNITS];
                float zg = sh_z2[ak + 2 * UNITS], zo = sh_z2[ak + 3 * UNITS];
                c2 = sigm_f(zf) * c2 + sigm_f(zi) * tanh_f(zg);
                sh_h2[ak] = sigm_f(zo) * tanh_f(c2);
            }
            if (has_u2) {
                float zi = sh_z2[64], zf = sh_z2[64 + UNITS];
                float zg = sh_z2[64 + 2 * UNITS], zo = sh_z2[64 + 3 * UNITS];
                c2x = sigm_f(zf) * c2x + sigm_f(zi) * tanh_f(zg);
                sh_h2[64] = sigm_f(zo) * tanh_f(c2x);
            }
        }
        __syncthreads();

        // ---- E: z3 = h2(t)@W + u3 + b ----
        if (is_dot) {
            dot33(sh_h2, wcol, a0, a1);
            sh_z3[j] = bj + hsum4(a0, a1);
        }
        __syncthreads();

        // ---- F: act L3 (->sh_h3, emit)  ||  z1(t+1) = zp + h1(t)@U ----
        if (is_dot) {
            a0 = 0ull; a1 = 0ull;
            dot33(sh_h1, ucol, a0, a1);
            sh_z1[j] = zp + hsum4(a0, a1);
        } else if (is_act) {
            {
                float zi = sh_z3[ak], zf = sh_z3[ak + UNITS];
                float zg = sh_z3[ak + 2 * UNITS], zo = sh_z3[ak + 3 * UNITS];
                c3 = sigm_f(zf) * c3 + sigm_f(zi) * tanh_f(zg);
                float hn = sigm_f(zo) * tanh_f(c3);
                sh_h3[ak] = hn;
                h3out[(size_t)t * UNITS + ak] = hn;
            }
            if (has_u2) {
                float zi = sh_z3[64], zf = sh_z3[64 + UNITS];
                float zg = sh_z3[64 + 2 * UNITS], zo = sh_z3[64 + 3 * UNITS];
                c3x = sigm_f(zf) * c3x + sigm_f(zi) * tanh_f(zg);
                float hn = sigm_f(zo) * tanh_f(c3x);
                sh_h3[64] = hn;
                h3out[(size_t)t * UNITS + 64] = hn;
            }
        }
        __syncthreads();
    }
}

// ---------------- kernel 3: out = ys @ Wd + bd  (parallel) ----------------
__global__ void __launch_bounds__(G4) dense_kernel(const float* __restrict__ Wd,
                                                   const float* __restrict__ bd,
                                                   float* __restrict__ out) {
    const int tid = threadIdx.x;           // 0..259
    const int rsub = tid / UNITS;          // 0..3
    const int jl = tid - rsub * UNITS;     // 0..64 -> output column

    unsigned long long wdcol[33];
#pragma unroll
    for (int m = 0; m < 32; m++)
        wdcol[m] = pack2(Wd[(2 * m) * UNITS + jl], Wd[(2 * m + 1) * UNITS + jl]);
    wdcol[32] = pack2(Wd[64 * UNITS + jl], 0.0f);
    const float bj = bd[jl];

    __shared__ __align__(16) float sh_y[4][68];
    if (tid < 12) sh_y[tid / 3][65 + tid % 3] = 0.0f;
    __syncthreads();

    for (size_t row0 = (size_t)blockIdx.x * 4; row0 < NROWS;
         row0 += (size_t)gridDim.x * 4) {
        __syncthreads();
        sh_y[rsub][jl] = g_h3[(row0 + rsub) * UNITS + jl];
        __syncthreads();
        unsigned long long a0 = 0ull, a1 = 0ull;
        dot33(sh_y[rsub], wdcol, a0, a1);
        out[(row0 + rsub) * UNITS + jl] = bj + hsum4(a0, a1);
    }
}

// ---------------- launch ----------------
extern "C" void kernel_launch(void* const* d_in, const int* in_sizes, int n_in,
                              void* d_out, int out_size) {
    const float* x  = (const float*)d_in[0];
    const float* W  = (const float*)d_in[1];
    const float* U  = (const float*)d_in[2];
    const float* b  = (const float*)d_in[3];
    const float* Wd = (const float*)d_in[4];
    const float* bd = (const float*)d_in[5];
    float* out = (float*)d_out;

    pre_kernel<<<1184, G4>>>(x, W, b);
    rec_kernel<<<BATCH, 352>>>(W, U, b);
    dense_kernel<<<1184, G4>>>(Wd, bd, out);
}